// round 17
// baseline (speedup 1.0000x reference)
#include <cuda_runtime.h>

#define SEQ   550
#define MID   100
#define G3    300   // 3*MID
#define EMBED 10
#define TPAD  560   // padded row length of transposed gi (140 float4s)

// Transposed input-side gate projections: g_giT[j*TPAD + t] = scale_j * (emb[t]·w_ih[j] + b_ih[j])
// scale_j = 0.5 for r/z rows (j < 200), 1.0 for n rows. Padded so the float4
// prefetch of block 137 (t=548..551) stays in bounds.
__device__ float g_giT[G3 * TPAD];

// ---------------------------------------------------------------------------
// Kernel 1: embedding lookup + input projection, written transposed+prescaled.
// One block per gate row j; threads sweep t -> coalesced stores.
// ---------------------------------------------------------------------------
__global__ void gi_kernel(const int* __restrict__ x,
                          const float* __restrict__ embed,
                          const float* __restrict__ w_ih,
                          const float* __restrict__ b_ih)
{
    const int j = blockIdx.x;     // 0..G3-1
    const int t = threadIdx.x;    // 0..SEQ-1
    const int tok = x[t];
    const float* e = embed + tok * EMBED;
    const float* w = w_ih + j * EMBED;
    float s = b_ih[j];
#pragma unroll
    for (int k = 0; k < EMBED; k++) s = fmaf(e[k], w[k], s);
    if (j < 2 * MID) s *= 0.5f;   // pre-scale for the half-angle sigmoid
    g_giT[j * TPAD + t] = s;
}

__device__ __forceinline__ unsigned long long pack2(float lo, float hi) {
    unsigned long long u;
    asm("mov.b64 %0, {%1, %2};" : "=l"(u) : "f"(lo), "f"(hi));
    return u;
}
__device__ __forceinline__ float tanh_mufu(float x) {
    float r;
    asm("tanh.approx.f32 %0, %1;" : "=f"(r) : "f"(x));
    return r;
}

// ---------------------------------------------------------------------------
// Kernel 2: persistent single-block GRU scan.
//
// 20 warps (640 threads), split-k x2. Each gate-row j (0..299) is owned by a
// LANE PAIR: half0 covers h[0..47] (+4 zero-weighted), half1 covers h[48..99].
// 26 FFMA2 per lane, 5 warps per SMSP -> fma-pipe floor 5*26*3 = 390 cyc/step.
//
// r/z rows carry a 0.5 factor baked into their weights, bias and gi, so the
// sigmoid is just tanh(pre+gi) (half-angle identity); lanes exchange RAW tau
// values and the n-lane reconstructs the gates with fmas that overlap the
// shfl latency. gi is consumed from a transposed array: one float4 LDG per
// lane per 4 steps. Exactly ONE __syncthreads per step (ping-pong h buffers).
// ---------------------------------------------------------------------------
__global__ void __launch_bounds__(640, 1)
gru_kernel(const float* __restrict__ hidden,
           const float* __restrict__ w_hh,
           const float* __restrict__ b_hh,
           const float* __restrict__ fc_w,
           const float* __restrict__ fc_b,
           float* __restrict__ out)
{
    __shared__ __align__(16) float sh_h[2][128];   // ping-pong hidden state
    __shared__ float red[24];

    const int tid  = threadIdx.x;
    const int wid  = tid >> 5;
    const int lane = tid & 31;
    const int grp  = lane / 6;            // 0..4 (lanes 30,31 -> 5, idle)
    const int sub  = lane - grp * 6;      // 0..5
    const int half = sub & 1;
    const int role = sub >> 1;            // 0=r, 1=z, 2=n
    const int col  = wid * 5 + grp;       // hidden column (<=100 for idle lanes)
    const int row  = col + MID * role;    // gate row (<=299; idle lanes <=100)
    const int tbase = grp * 6;            // lane of sub0 in this triplet

    // 0.5 sigmoid factor baked into weights + bias for r/z rows.
    const float wscale = (role < 2) ? 0.5f : 1.0f;

    // --- load this lane's 52-float weight slice as 26 packed pairs ---
    unsigned long long w2[26];
    {
        const float4* wp =
            reinterpret_cast<const float4*>(w_hh + row * MID + half * 48);
#pragma unroll
        for (int i = 0; i < 13; i++) {
            float4 v = wp[i];
            w2[2 * i]     = pack2(v.x * wscale, v.y * wscale);
            w2[2 * i + 1] = pack2(v.z * wscale, v.w * wscale);
        }
        if (half == 0) { w2[24] = 0ull; w2[25] = 0ull; }
    }
    const float bhh = (half == 0) ? b_hh[row] * wscale : 0.f;

    // --- init hidden state (buffer 0) ---
    if (tid < MID) sh_h[0][tid] = hidden[tid];
    float h_old = (sub == 4) ? hidden[col] : 0.f;

    const float4* giT4 = reinterpret_cast<const float4*>(g_giT + row * TPAD);

    // One GRU step. hin/hout are the ping-pong buffers.
    auto step = [&](float gi_cur, const float* hin, float* hout) {
        const ulonglong2* hp = reinterpret_cast<const ulonglong2*>(
            reinterpret_cast<const char*>(hin) + half * 192);
        unsigned long long a0 = pack2(bhh, 0.f);
        unsigned long long a1 = 0ull, a2 = 0ull, a3 = 0ull;
#pragma unroll
        for (int i = 0; i < 12; i += 2) {
            ulonglong2 h0 = hp[i];
            ulonglong2 h1 = hp[i + 1];
            asm("fma.rn.f32x2 %0, %1, %2, %0;" : "+l"(a0) : "l"(w2[2 * i    ]), "l"(h0.x));
            asm("fma.rn.f32x2 %0, %1, %2, %0;" : "+l"(a1) : "l"(w2[2 * i + 1]), "l"(h0.y));
            asm("fma.rn.f32x2 %0, %1, %2, %0;" : "+l"(a2) : "l"(w2[2 * i + 2]), "l"(h1.x));
            asm("fma.rn.f32x2 %0, %1, %2, %0;" : "+l"(a3) : "l"(w2[2 * i + 3]), "l"(h1.y));
        }
        {
            ulonglong2 h12 = hp[12];
            asm("fma.rn.f32x2 %0, %1, %2, %0;" : "+l"(a0) : "l"(w2[24]), "l"(h12.x));
            asm("fma.rn.f32x2 %0, %1, %2, %0;" : "+l"(a1) : "l"(w2[25]), "l"(h12.y));
        }
        unsigned long long s01, s23, sp;
        asm("add.rn.f32x2 %0, %1, %2;" : "=l"(s01) : "l"(a0), "l"(a1));
        asm("add.rn.f32x2 %0, %1, %2;" : "=l"(s23) : "l"(a2), "l"(a3));
        asm("add.rn.f32x2 %0, %1, %2;" : "=l"(sp)  : "l"(s01), "l"(s23));
        union { unsigned long long u; float2 f; } cc; cc.u = sp;
        float s = cc.f.x + cc.f.y;
        s += __shfl_xor_sync(0xffffffffu, s, 1);   // combine the two k-halves
        const float pre = s;                        // r/z: 0.5*(dot+b); n: dot+b

        // r/z lanes: tau = tanh(0.5*(dot+b) + 0.5*gi)  [sigmoid half-angle]
        const float val = tanh_mufu(pre + gi_cur);

        const float tr = __shfl_sync(0xffffffffu, val, tbase);      // tau_r
        const float tz = __shfl_sync(0xffffffffu, val, tbase + 2);  // tau_z

        if (sub == 4) {
            // computable during shfl latency:
            const float c  = 0.5f * pre;            // 0.5*pre_n
            const float d  = gi_cur + c;
            const float zc = fmaf(0.5f, tz, 0.5f);  // z
            const float g  = h_old * zc;            // z*h
            const float omz = 1.f - zc;             // 1-z
            // critical chain: fma -> tanh -> fma
            const float xa = fmaf(tr, c, d);        // gi_n + r*pre_n
            const float n  = tanh_mufu(xa);
            h_old = fmaf(n, omz, g);                // (1-z)*n + z*h
            hout[col] = h_old;
        }
        __syncthreads();
    };

    float4 cur = giT4[0];
    __syncthreads();

    // 550 = 137*4 + 2 steps; gi arrives as one float4 per 4 steps.
#pragma unroll 1
    for (int blk = 0; blk < 137; blk++) {
        float4 nxt = giT4[blk + 1];                // prefetch next block
        step(cur.x, sh_h[0], sh_h[1]);
        step(cur.y, sh_h[1], sh_h[0]);
        step(cur.z, sh_h[0], sh_h[1]);
        step(cur.w, sh_h[1], sh_h[0]);
        cur = nxt;
    }
    step(cur.x, sh_h[0], sh_h[1]);                 // t = 548
    step(cur.y, sh_h[1], sh_h[0]);                 // t = 549  -> final h in sh_h[0]

    // ---------------- epilogue: sigmoid(relu(h) @ fc_w^T + fc_b) ----------------
    const float* hf = sh_h[0];
    float p = 0.f;
    if (tid < MID) p = fmaxf(hf[tid], 0.f) * fc_w[tid];
#pragma unroll
    for (int o = 16; o; o >>= 1) p += __shfl_xor_sync(0xffffffffu, p, o);
    if (lane == 0) red[wid] = p;
    __syncthreads();
    if (tid == 0) {
        float sfin = fc_b[0];
#pragma unroll
        for (int w = 0; w < 20; w++) sfin += red[w];
        out[0] = __fdividef(1.f, 1.f + __expf(-sfin));
    }
}

// ---------------------------------------------------------------------------
// Inputs (metadata order): x, hidden, embed_table, w_ih, w_hh, b_ih, b_hh,
//                          fc_w, fc_b.  Output: float32[1].
// ---------------------------------------------------------------------------
extern "C" void kernel_launch(void* const* d_in, const int* in_sizes, int n_in,
                              void* d_out, int out_size)
{
    const int*   x      = (const int*)  d_in[0];
    const float* hidden = (const float*)d_in[1];
    const float* embed  = (const float*)d_in[2];
    const float* w_ih   = (const float*)d_in[3];
    const float* w_hh   = (const float*)d_in[4];
    const float* b_ih   = (const float*)d_in[5];
    const float* b_hh   = (const float*)d_in[6];
    const float* fc_w   = (const float*)d_in[7];
    const float* fc_b   = (const float*)d_in[8];

    gi_kernel<<<G3, SEQ>>>(x, embed, w_ih, b_ih);
    gru_kernel<<<1, 640>>>(hidden, w_hh, b_hh, fc_w, fc_b, (float*)d_out);
}